// round 15
// baseline (speedup 1.0000x reference)
#include <cuda_runtime.h>
#include <cuda_fp16.h>
#include <stdint.h>
#include <stddef.h>

#define BATCH 2
#define NSEQ  1024
#define DIM   1024
#define NH    16
#define DH    64
#define QE_S  151
#define QE_PAD 152

#define BM 128
#define BK 32
#define BKP 40                       // padded row: 40 halfs = 80 B
#define STAGES 3
#define MATB (BM*BKP*2)              // 10240 B per A matrix per stage

// ---------------- static scratch (no cudaMalloc allowed) ----------------
__device__ __align__(128) float  g_tmpQ[BATCH*NSEQ*DIM];
__device__ __align__(128) float  g_tmpV[BATCH*NSEQ*DIM];
__device__ __align__(128) __half g_xh[BATCH*NSEQ*DIM],  g_xl[BATCH*NSEQ*DIM];
__device__ __align__(128) __half g_Wh[4][DIM*DIM];                  // q,k,v,o (hi only)
__device__ __align__(128) __half g_Erh[NSEQ*DH];
__device__ __align__(128) __half g_Qh[BATCH*NSEQ*DIM], g_Ql[BATCH*NSEQ*DIM];
__device__ __align__(128) __half g_Kh[BATCH*NSEQ*DIM];
__device__ __align__(128) __half g_Vth[BATCH*NH*DH*NSEQ];           // [b][h][d][j]
__device__ __align__(128) __half g_AOh[BATCH*NSEQ*DIM];
__device__ __align__(128) float  g_QE[BATCH*NH*NSEQ*QE_PAD];
__device__ __align__(128) __half g_Sh [BATCH*NH*NSEQ*NSEQ];         // scores, fp16
__device__ __align__(128) __half g_QErh[BATCH*NH*NSEQ*NSEQ];        // QEr, fp16
__device__ __align__(128) __half g_Ph[BATCH*NH*NSEQ*NSEQ];
__device__ __align__(128) float  g_rsum[BATCH*NH*NSEQ];

// ---------------- helpers ----------------
__device__ __forceinline__ void mma16816(float c[4], const uint32_t a[4],
                                         uint32_t b0, uint32_t b1)
{
    asm volatile(
        "mma.sync.aligned.m16n8k16.row.col.f32.f16.f16.f32 "
        "{%0,%1,%2,%3}, {%4,%5,%6,%7}, {%8,%9}, {%0,%1,%2,%3};\n"
        : "+f"(c[0]), "+f"(c[1]), "+f"(c[2]), "+f"(c[3])
        : "r"(a[0]), "r"(a[1]), "r"(a[2]), "r"(a[3]), "r"(b0), "r"(b1));
}

__device__ __forceinline__ void ldsm4(uint32_t* r, uint32_t addr)
{
    asm volatile("ldmatrix.sync.aligned.m8n8.x4.shared.b16 {%0,%1,%2,%3}, [%4];\n"
                 : "=r"(r[0]), "=r"(r[1]), "=r"(r[2]), "=r"(r[3]) : "r"(addr));
}

// per-z-segment GEMM descriptor
struct GSeg {
    const __half* Bh;     // B operand (fp16 hi)
    float*  C;            // optional fp32 out
    __half* Dh;           // optional fp16 hi out
    __half* Dl;           // optional fp16 lo out
    int  ldb;
    long sbB, sbH;        // B (batch, head) strides
    int  mode;            // 0 none, 1 causal skip, 2 anti-diag skip, 3 causal K-limit
};

// ========== pipelined fp16 split GEMM: C[M,N] = A[M,K] @ B[N,K]^T ==========
// NPASS=2: A pre-split (hi,lo), product = Ah*Bh + Al*Bh.  NPASS=1: plain Ah*Bh.
// blockIdx.z selects segment (s0/s1/s2) via zs1/zs2; local z -> (zb,zh).
// Rsum != null: epilogue scales output row r by 1/Rsum[lz*NSEQ + r].
template<int NI, int NPASS>
__global__ __launch_bounds__(256, 2)
void gemm_fp16(const __half* __restrict__ Ah, const __half* __restrict__ Al,
               GSeg s0, GSeg s1, GSeg s2, int zs1, int zs2,
               int N, int K, int lda, int ldc,
               long saB, long saH, long scB, long scH, int Hc,
               const float* __restrict__ Rsum)
{
    constexpr int BN   = 32 * NI;
    constexpr int BMAT = BN * BKP * 2;           // B bytes per stage
    constexpr int STB  = NPASS * MATB + BMAT;    // stage bytes
    constexpr int ACH  = 512 * NPASS;            // A 16B chunks per stage
    constexpr int NCH  = ACH + BN * 4;           // total 16B chunks per stage

    extern __shared__ char smem[];
    GSeg sg; int lz;
    {
        int z = blockIdx.z;
        if (z < zs1)      { sg = s0; lz = z; }
        else if (z < zs2) { sg = s1; lz = z - zs1; }
        else              { sg = s2; lz = z - zs2; }
    }
    int zb = lz / Hc, zh = lz - zb * Hc;
    Ah += zb*saB + zh*saH;
    if (NPASS == 2) Al += zb*saB + zh*saH;
    const __half* Bh = sg.Bh + zb*sg.sbB + zh*sg.sbH;
    float*  C  = sg.C;
    __half* Dh = sg.Dh;
    __half* Dl = sg.Dl;
    int ldb = sg.ldb, mode = sg.mode;
    size_t cOff = (size_t)zb * scB + (size_t)zh * scH;

    int m0 = blockIdx.y * BM, n0 = blockIdx.x * BN;
    if (mode == 1 && n0 >= m0 + BM) return;
    if (mode == 2 && (m0 + n0 + BM + BN - 2) < (N - 1)) return;
    int Kt = (mode == 3) ? (K < m0 + BM ? K : m0 + BM) : K;
    int nT = Kt / BK;

    uint32_t su = (uint32_t)__cvta_generic_to_shared(smem);
    int tid = threadIdx.x, warp = tid >> 5, lane = tid & 31;
    int wm = warp >> 2, wn = warp & 3;           // 2 x 4 warps; warp tile 64 x (8*NI)

    auto load_tile = [&](int t, int s) {
        int k0 = t * BK;
        uint32_t base = su + s * STB;
        #pragma unroll
        for (int it = 0; it < NCH / 256; it++) {
            int c = tid + it * 256;
            const __half* src; uint32_t off; int rc, rowBase, ld;
            if (c < 512)                       { src = Ah; off = 0;          rc = c;       rowBase = m0; ld = lda; }
            else if (NPASS == 2 && c < 1024)   { src = Al; off = MATB;       rc = c - 512; rowBase = m0; ld = lda; }
            else                               { src = Bh; off = NPASS*MATB; rc = c - ACH; rowBase = n0; ld = ldb; }
            int row = rc >> 2, ch = rc & 3;      // 4 x 16B chunks per 64B row
            uint32_t dst = base + off + row * (BKP*2) + ch * 16;
            const void* p = src + (size_t)(rowBase + row) * ld + (k0 + ch * 8);
            asm volatile("cp.async.cg.shared.global [%0], [%1], 16;" :: "r"(dst), "l"(p));
        }
    };

    float acc[4][NI][4];
    #pragma unroll
    for (int i = 0; i < 4; i++)
        #pragma unroll
        for (int j = 0; j < NI; j++)
            #pragma unroll
            for (int u = 0; u < 4; u++) acc[i][j][u] = 0.f;

    #pragma unroll
    for (int s = 0; s < STAGES - 1; s++) {
        if (s < nT) load_tile(s, s);
        asm volatile("cp.async.commit_group;" ::: "memory");
    }

    int aoffBase = ((wm*64 + (lane & 15)) * BKP + ((lane >> 4) << 3)) * 2;
    int bq = lane >> 3, brr = lane & 7;
    int boffBase = ((wn*8*NI + brr + ((bq >> 1) << 3)) * BKP + ((bq & 1) << 3)) * 2;

    for (int t = 0; t < nT; t++) {
        asm volatile("cp.async.wait_group %0;" :: "n"(STAGES - 2));
        __syncthreads();
        int nxt = t + STAGES - 1;
        if (nxt < nT) load_tile(nxt, nxt % STAGES);
        asm volatile("cp.async.commit_group;" ::: "memory");

        uint32_t sb = su + (t % STAGES) * STB;
        #pragma unroll
        for (int ks = 0; ks < BK; ks += 16) {
            uint32_t bf[NI][2];
            #pragma unroll
            for (int np = 0; np < NI/2; np++) {
                uint32_t bt[4];
                ldsm4(bt, sb + NPASS*MATB + boffBase + (np*16*BKP + ks) * 2);
                bf[2*np][0]   = bt[0]; bf[2*np][1]   = bt[1];
                bf[2*np+1][0] = bt[2]; bf[2*np+1][1] = bt[3];
            }
            #pragma unroll
            for (int pass = 0; pass < NPASS; pass++) {
                uint32_t af[4][4];
                #pragma unroll
                for (int mi = 0; mi < 4; mi++)
                    ldsm4(af[mi], sb + pass*MATB + aoffBase + (mi*16*BKP + ks) * 2);
                #pragma unroll
                for (int mi = 0; mi < 4; mi++)
                    #pragma unroll
                    for (int ni = 0; ni < NI; ni++)
                        mma16816(acc[mi][ni], af[mi], bf[ni][0], bf[ni][1]);
            }
        }
    }

    // epilogue (optional deferred-softmax row scaling)
    long rsOff = (long)lz * NSEQ;
    int g = lane >> 2, tq = lane & 3;
    #pragma unroll
    for (int mi = 0; mi < 4; mi++) {
        int r0 = m0 + wm*64 + mi*16 + g;
        float inv0 = 1.f, inv8 = 1.f;
        if (Rsum) {
            inv0 = __frcp_rn(Rsum[rsOff + r0]);
            inv8 = __frcp_rn(Rsum[rsOff + r0 + 8]);
        }
        #pragma unroll
        for (int ni = 0; ni < NI; ni++) {
            int c0 = n0 + wn*8*NI + ni*8 + 2*tq;
            #pragma unroll
            for (int hrow = 0; hrow < 2; hrow++) {
                size_t o = cOff + (size_t)(r0 + 8*hrow) * ldc + c0;
                float sc = hrow ? inv8 : inv0;
                float v0 = acc[mi][ni][2*hrow] * sc, v1 = acc[mi][ni][2*hrow + 1] * sc;
                if (C) *(float2*)(C + o) = make_float2(v0, v1);
                if (Dh) {
                    __half2 hh;
                    hh.x = __float2half_rn(v0);  hh.y = __float2half_rn(v1);
                    *(__half2*)(Dh + o) = hh;
                    if (Dl) {
                        __half2 ll;
                        ll.x = __float2half_rn(v0 - __half2float(hh.x));
                        ll.y = __float2half_rn(v1 - __half2float(hh.y));
                        *(__half2*)(Dl + o) = ll;
                    }
                }
            }
        }
    }
}

// ---------------- merged input split: fp32 -> fp16 hi (+ optional lo) ----------------
struct SJob { const float* s; __half* h; __half* l; int n4; };

__global__ void split_multi(SJob j0, SJob j1, SJob j2, SJob j3, SJob j4, SJob j5)
{
    SJob j;
    switch (blockIdx.y) {
        case 0: j = j0; break; case 1: j = j1; break; case 2: j = j2; break;
        case 3: j = j3; break; case 4: j = j4; break; default: j = j5; break;
    }
    int i = blockIdx.x * 256 + threadIdx.x;
    if (i >= j.n4) return;
    float4 v = ((const float4*)j.s)[i];
    __half2 h01, h23;
    h01.x = __float2half_rn(v.x);  h01.y = __float2half_rn(v.y);
    h23.x = __float2half_rn(v.z);  h23.y = __float2half_rn(v.w);
    ((__half2*)j.h)[2*i]   = h01;
    ((__half2*)j.h)[2*i+1] = h23;
    if (j.l) {
        __half2 l01, l23;
        l01.x = __float2half_rn(v.x - __half2float(h01.x));
        l01.y = __float2half_rn(v.y - __half2float(h01.y));
        l23.x = __float2half_rn(v.z - __half2float(h23.x));
        l23.y = __float2half_rn(v.w - __half2float(h23.y));
        ((__half2*)j.l)[2*i]   = l01;
        ((__half2*)j.l)[2*i+1] = l23;
    }
}

// ---------------- V transpose: tmpV (b, j, h*64+d) -> Vth [b][h][d][j] fp16 ----------------
__global__ void transpose_v(const float* __restrict__ V)
{
    __shared__ float tile[32][33];
    int bh = blockIdx.z;
    int b = bh >> 4, h = bh & 15;
    int j0 = blockIdx.x * 32, d0 = blockIdx.y * 32;
    for (int r = threadIdx.y; r < 32; r += 8)
        tile[r][threadIdx.x] =
            V[((size_t)(b * NSEQ) + j0 + r) * DIM + h * DH + d0 + threadIdx.x];
    __syncthreads();
    for (int r = threadIdx.y; r < 32; r += 8) {
        size_t o = ((size_t)(bh * DH) + d0 + r) * NSEQ + j0 + threadIdx.x;
        g_Vth[o] = __float2half_rn(tile[threadIdx.x][r]);
    }
}

// ================= QE: smem-blocked, coalesced =================
#define QE_SMEM (39296 + 64*64*4)     // tabs[151][65] (pad) + q[64][64]

__global__ __launch_bounds__(256)
void qe_kernel2(const float* __restrict__ Q,
                const float* __restrict__ Tb, const float* __restrict__ Tp,
                const float* __restrict__ To, const float* __restrict__ Ts)
{
    extern __shared__ float sm[];
    float* tabs = sm;                 // [151][65]
    float* qs   = sm + 9824;          // [64][64]
    int i0 = blockIdx.x * 64, h = blockIdx.y, b = blockIdx.z;
    int tid = threadIdx.x;

    for (int idx = tid; idx < QE_S * 64; idx += 256) {
        int s = idx >> 6, d = idx & 63;
        const float* tab; int r, rows;
        if (s < 17)       { tab = Tb; r = s;       rows = 16; }
        else if (s < 113) { tab = Tp; r = s - 17;  rows = 95; }
        else if (s < 138) { tab = To; r = s - 113; rows = 24; }
        else              { tab = Ts; r = s - 138; rows = 12; }
        tabs[s * 65 + d] = (r < rows) ? tab[r * 64 + d] : 0.f;
    }
    for (int idx = tid; idx < 64 * 64; idx += 256) {
        int ii = idx >> 6, d = idx & 63;
        qs[idx] = Q[((size_t)(b * NSEQ) + i0 + ii) * DIM + h * DH + d];
    }
    __syncthreads();

    int ty = tid >> 5, tx = tid & 31;
    float acc[5][8];
    #pragma unroll
    for (int si = 0; si < 5; si++)
        #pragma unroll
        for (int ii = 0; ii < 8; ii++) acc[si][ii] = 0.f;
    int sc[5];
    #pragma unroll
    for (int si = 0; si < 5; si++) { int s = tx + si * 32; sc[si] = (s < QE_S) ? s : 0; }

    const float* qrow = qs + ty * 8 * 64;
    #pragma unroll 4
    for (int d = 0; d < 64; d++) {
        float q8[8];
        #pragma unroll
        for (int ii = 0; ii < 8; ii++) q8[ii] = qrow[ii * 64 + d];
        #pragma unroll
        for (int si = 0; si < 5; si++) {
            float tv = tabs[sc[si] * 65 + d];
            #pragma unroll
            for (int ii = 0; ii < 8; ii++) acc[si][ii] += tv * q8[ii];
        }
    }

    size_t base = ((size_t)(b * NH + h) * NSEQ + i0 + ty * 8) * QE_PAD;
    #pragma unroll
    for (int si = 0; si < 5; si++) {
        int s = tx + si * 32;
        if (s < QE_S) {
            #pragma unroll
            for (int ii = 0; ii < 8; ii++)
                g_QE[base + (size_t)ii * QE_PAD + s] = acc[si][ii];
        }
    }
}

// ---------------- fused bias + skew + softmax (unnormalized) ----------------
// Reads fp16 scores + fp16 QEr; writes P = exp(scores - rowmax) as fp16 (hi only)
// and the row sum to g_rsum; normalization happens in the P@V epilogue.
__global__ __launch_bounds__(256)
void bias_softmax(const int* __restrict__ rb, const int* __restrict__ rp,
                  const int* __restrict__ ro, const int* __restrict__ rs)
{
    int i = blockIdx.x, b = blockIdx.y;
    __shared__ short sIdx[4][NSEQ];
    __shared__ float row[NSEQ];
    __shared__ float qe[QE_PAD];
    __shared__ float red[8];
    int tid = threadIdx.x;
    int Li = i + 1;
    int jEnd = (Li + 127) & ~127;
    size_t iBase = ((size_t)(b * NSEQ) + i) * NSEQ;

    for (int j = tid; j < Li; j += 256) {
        sIdx[0][j] = (short)rb[iBase + j];
        sIdx[1][j] = (short)(17  + rp[iBase + j]);
        sIdx[2][j] = (short)(113 + ro[iBase + j]);
        sIdx[3][j] = (short)(138 + rs[iBase + j]);
    }

    for (int h = 0; h < NH; h++) {
        size_t base  = (size_t)((b * NH + h) * NSEQ) + i;
        size_t sBase = base * NSEQ;
        __syncthreads();
        if (tid < QE_S) qe[tid] = g_QE[base * QE_PAD + tid];
        __syncthreads();

        const __half* qer = &g_QErh[sBase + (NSEQ - 1 - i)];
        float lmax = -3.0e38f;
        for (int j = tid; j < Li; j += 256) {
            float v = __half2float(g_Sh[sBase + j]) + __half2float(qer[j])
                    + qe[sIdx[0][j]] + qe[sIdx[1][j]] + qe[sIdx[2][j]] + qe[sIdx[3][j]];
            v *= 0.125f;
            row[j] = v;
            lmax = fmaxf(lmax, v);
        }
        #pragma unroll
        for (int o = 16; o > 0; o >>= 1)
            lmax = fmaxf(lmax, __shfl_xor_sync(0xffffffffu, lmax, o));
        if ((tid & 31) == 0) red[tid >> 5] = lmax;
        __syncthreads();
        float m = red[0];
        #pragma unroll
        for (int w = 1; w < 8; w++) m = fmaxf(m, red[w]);

        // exp + write (unnormalized, fp16 hi only) + sum, single pass
        float lsum = 0.f;
        for (int j = tid; j < jEnd; j += 256) {
            float e = (j < Li) ? __expf(row[j] - m) : 0.f;
            g_Ph[sBase + j] = __float2half_rn(e);
            lsum += e;
        }
        #pragma unroll
        for (int o = 16; o > 0; o >>= 1) lsum += __shfl_xor_sync(0xffffffffu, lsum, o);
        if ((tid & 31) == 0) red[tid >> 5] = lsum;
        __syncthreads();
        if (tid == 0) {
            float tot = 0.f;
            #pragma unroll
            for (int w = 0; w < 8; w++) tot += red[w];
            g_rsum[(size_t)(b * NH + h) * NSEQ + i] = tot;
        }
    }
}

// ---------------- host orchestration ----------------
extern "C" void kernel_launch(void* const* d_in, const int* in_sizes, int n_in,
                              void* d_out, int out_size)
{
    (void)in_sizes; (void)n_in; (void)out_size;
    const float* x   = (const float*)d_in[0];
    const int*   rb  = (const int*)d_in[1];
    const int*   rp  = (const int*)d_in[2];
    const int*   ro  = (const int*)d_in[3];
    const int*   rs  = (const int*)d_in[4];
    const float* Wq  = (const float*)d_in[5];
    const float* Wk  = (const float*)d_in[6];
    const float* Wv  = (const float*)d_in[7];
    const float* Wo  = (const float*)d_in[8];
    const float* Er  = (const float*)d_in[9];
    const float* Erb = (const float*)d_in[10];
    const float* Erp = (const float*)d_in[11];
    const float* Ero = (const float*)d_in[12];
    const float* Ers = (const float*)d_in[13];
    float* out = (float*)d_out;

    const int SMEM_42 = STAGES * (2*MATB + 128*BKP*2);   // 92160
    const int SMEM_41 = STAGES * (1*MATB + 128*BKP*2);   // 61440
    const int SMEM_21 = STAGES * (1*MATB +  64*BKP*2);   // 46080
    cudaFuncSetAttribute((const void*)gemm_fp16<4,2>, cudaFuncAttributeMaxDynamicSharedMemorySize, SMEM_42);
    cudaFuncSetAttribute((const void*)gemm_fp16<4,1>, cudaFuncAttributeMaxDynamicSharedMemorySize, SMEM_41);
    cudaFuncSetAttribute((const void*)gemm_fp16<2,1>, cudaFuncAttributeMaxDynamicSharedMemorySize, SMEM_21);
    cudaFuncSetAttribute((const void*)qe_kernel2,     cudaFuncAttributeMaxDynamicSharedMemorySize, QE_SMEM);

    float *pTmpQ, *pTmpV, *pRsum;
    __half *pxh, *pxl, *pWh, *pErh, *pQh, *pQl, *pKh, *pVth, *pAOh, *pPh, *pSh, *pQErh;
    cudaGetSymbolAddress((void**)&pTmpQ, g_tmpQ);
    cudaGetSymbolAddress((void**)&pTmpV, g_tmpV);
    cudaGetSymbolAddress((void**)&pSh,   g_Sh);
    cudaGetSymbolAddress((void**)&pQErh, g_QErh);
    cudaGetSymbolAddress((void**)&pRsum, g_rsum);
    cudaGetSymbolAddress((void**)&pxh,   g_xh);
    cudaGetSymbolAddress((void**)&pxl,   g_xl);
    cudaGetSymbolAddress((void**)&pWh,   g_Wh);
    cudaGetSymbolAddress((void**)&pErh,  g_Erh);
    cudaGetSymbolAddress((void**)&pQh,   g_Qh);
    cudaGetSymbolAddress((void**)&pQl,   g_Ql);
    cudaGetSymbolAddress((void**)&pKh,   g_Kh);
    cudaGetSymbolAddress((void**)&pVth,  g_Vth);
    cudaGetSymbolAddress((void**)&pAOh,  g_AOh);
    cudaGetSymbolAddress((void**)&pPh,   g_Ph);

    const int MB  = BATCH * NSEQ;   // 2048
    const int WSZ = DIM * DIM;

    long saB = (long)NSEQ * DIM, saH = DH;
    long scB = (long)NH * NSEQ * NSEQ, scH = (long)NSEQ * NSEQ;
    dim3 blk(256);

    // 0) split inputs (x needs hi+lo; W/Er hi only)
    {
        SJob j0 = { x,  pxh,         pxl,     MB * DIM / 4 };
        SJob j1 = { Wq, pWh + 0*WSZ, nullptr, WSZ / 4 };
        SJob j2 = { Wk, pWh + 1*WSZ, nullptr, WSZ / 4 };
        SJob j3 = { Wv, pWh + 2*WSZ, nullptr, WSZ / 4 };
        SJob j4 = { Wo, pWh + 3*WSZ, nullptr, WSZ / 4 };
        SJob j5 = { Er, pErh,        nullptr, NSEQ * DH / 4 };
        split_multi<<<dim3(2048, 6), 256>>>(j0, j1, j2, j3, j4, j5);
    }

    // 1) fused Q/K/V projections: z=0 Q, z=1 K, z=2 V
    {
        GSeg sq = { pWh + 0*WSZ, pTmpQ, pQh, pQl, DIM, 0, 0, 0 };
        GSeg sk = { pWh + 1*WSZ, nullptr, pKh, nullptr, DIM, 0, 0, 0 };
        GSeg sv = { pWh + 2*WSZ, pTmpV, nullptr, nullptr, DIM, 0, 0, 0 };
        gemm_fp16<4,2><<<dim3(DIM/128, MB/BM, 3), blk, SMEM_42>>>(
            pxh, pxl, sq, sk, sv, 1, 2,
            DIM, DIM, DIM, DIM, 0, 0, 0, 0, 1, nullptr);
    }
    // 2) QE tables
    qe_kernel2<<<dim3(NSEQ / 64, NH, BATCH), 256, QE_SMEM>>>(pTmpQ, Erb, Erp, Ero, Ers);
    // 3) transpose V -> fp16
    transpose_v<<<dim3(NSEQ / 32, DH / 32, BATCH * NH), dim3(32, 8)>>>(pTmpV);
    // 4) fused scores (z<32, causal skip) + QEr (z>=32, anti-diag skip), both fp16 out
    {
        GSeg ss  = { pKh,  nullptr, pSh,   nullptr, DIM, saB, saH, 1 };
        GSeg sqe = { pErh, nullptr, pQErh, nullptr, DH,  0,   0,   2 };
        gemm_fp16<4,2><<<dim3(NSEQ/128, NSEQ/BM, 64), blk, SMEM_42>>>(
            pQh, pQl, ss, sqe, ss, 32, 64,
            NSEQ, DH, DIM, NSEQ, saB, saH, scB, scH, NH, nullptr);
    }
    // 5) bias + softmax -> unnormalized P (fp16) + row sums
    bias_softmax<<<dim3(NSEQ, BATCH), 256>>>(rb, rp, ro, rs);
    // 6) attn_out = (P @ V) / rsum  (single-pass A, BN=64, causal K-limit, fp16 out)
    {
        GSeg sv = { pVth, nullptr, pAOh, nullptr, NSEQ,
                    (long)NH * DH * NSEQ, (long)DH * NSEQ, 3 };
        gemm_fp16<2,1><<<dim3(1, NSEQ/BM, BATCH*NH), blk, SMEM_21>>>(
            pPh, nullptr, sv, sv, sv, 32, 64,
            DH, NSEQ, NSEQ, DIM,
            scB, scH, (long)NSEQ * DIM, (long)DH, NH, pRsum);
    }
    // 7) out = attn_out @ Wo^T  (single-pass A: AO fp16 only)
    {
        GSeg so = { pWh + 3*WSZ, out, nullptr, nullptr, DIM, 0, 0, 0 };
        gemm_fp16<4,1><<<dim3(DIM/128, MB/BM, 1), blk, SMEM_41>>>(
            pAOh, nullptr, so, so, so, 1, 2,
            DIM, DIM, DIM, DIM, 0, 0, 0, 0, 1, nullptr);
    }
}

// round 16
// speedup vs baseline: 1.4145x; 1.4145x over previous
#include <cuda_runtime.h>
#include <cuda_fp16.h>
#include <stdint.h>
#include <stddef.h>

#define BATCH 2
#define NSEQ  1024
#define DIM   1024
#define NH    16
#define DH    64
#define QE_S  151
#define QE_PAD 152

#define BM 128
#define BK 32
#define BKP 40                       // padded row: 40 halfs = 80 B
#define STAGES 3
#define MATB (BM*BKP*2)              // 10240 B per A matrix per stage

// ---------------- static scratch (no cudaMalloc allowed) ----------------
__device__ __align__(128) float  g_tmpQ[BATCH*NSEQ*DIM];
__device__ __align__(128) float  g_tmpV[BATCH*NSEQ*DIM];
__device__ __align__(128) __half g_xh[BATCH*NSEQ*DIM],  g_xl[BATCH*NSEQ*DIM];
__device__ __align__(128) __half g_Wh[4][DIM*DIM];                  // q,k,v,o (hi only)
__device__ __align__(128) __half g_Erh[NSEQ*DH];
__device__ __align__(128) __half g_Qh[BATCH*NSEQ*DIM], g_Ql[BATCH*NSEQ*DIM];
__device__ __align__(128) __half g_Kh[BATCH*NSEQ*DIM];
__device__ __align__(128) __half g_Vth[BATCH*NH*DH*NSEQ];           // [b][h][d][j]
__device__ __align__(128) __half g_AOh[BATCH*NSEQ*DIM];
__device__ __align__(128) float  g_QE[BATCH*NH*NSEQ*QE_PAD];
__device__ __align__(128) float  g_S [BATCH*NH*NSEQ*NSEQ];          // scores, fp32 (reverted)
__device__ __align__(128) float  g_QEr[BATCH*NH*NSEQ*NSEQ];         // QEr, fp32 (reverted)
__device__ __align__(128) __half g_Ph[BATCH*NH*NSEQ*NSEQ];
__device__ __align__(128) float  g_rsum[BATCH*NH*NSEQ];

// ---------------- helpers ----------------
__device__ __forceinline__ void mma16816(float c[4], const uint32_t a[4],
                                         uint32_t b0, uint32_t b1)
{
    asm volatile(
        "mma.sync.aligned.m16n8k16.row.col.f32.f16.f16.f32 "
        "{%0,%1,%2,%3}, {%4,%5,%6,%7}, {%8,%9}, {%0,%1,%2,%3};\n"
        : "+f"(c[0]), "+f"(c[1]), "+f"(c[2]), "+f"(c[3])
        : "r"(a[0]), "r"(a[1]), "r"(a[2]), "r"(a[3]), "r"(b0), "r"(b1));
}

__device__ __forceinline__ void ldsm4(uint32_t* r, uint32_t addr)
{
    asm volatile("ldmatrix.sync.aligned.m8n8.x4.shared.b16 {%0,%1,%2,%3}, [%4];\n"
                 : "=r"(r[0]), "=r"(r[1]), "=r"(r[2]), "=r"(r[3]) : "r"(addr));
}

// per-z-segment GEMM descriptor
struct GSeg {
    const __half* Bh;     // B operand (fp16 hi)
    float*  C;            // optional fp32 out
    __half* Dh;           // optional fp16 hi out
    __half* Dl;           // optional fp16 lo out
    int  ldb;
    long sbB, sbH;        // B (batch, head) strides
    int  mode;            // 0 none, 1 causal skip, 2 anti-diag skip, 3 causal K-limit
};

// ========== pipelined fp16 split GEMM: C[M,N] = A[M,K] @ B[N,K]^T ==========
// NPASS=2: A pre-split (hi,lo), product = Ah*Bh + Al*Bh.  NPASS=1: plain Ah*Bh.
// blockIdx.z selects segment (s0/s1/s2) via zs1/zs2; local z -> (zb,zh).
// Rsum != null: epilogue scales output row r by 1/Rsum[lz*NSEQ + r].
template<int NI, int NPASS>
__global__ __launch_bounds__(256, 2)
void gemm_fp16(const __half* __restrict__ Ah, const __half* __restrict__ Al,
               GSeg s0, GSeg s1, GSeg s2, int zs1, int zs2,
               int N, int K, int lda, int ldc,
               long saB, long saH, long scB, long scH, int Hc,
               const float* __restrict__ Rsum)
{
    constexpr int BN   = 32 * NI;
    constexpr int BMAT = BN * BKP * 2;           // B bytes per stage
    constexpr int STB  = NPASS * MATB + BMAT;    // stage bytes
    constexpr int ACH  = 512 * NPASS;            // A 16B chunks per stage
    constexpr int NCH  = ACH + BN * 4;           // total 16B chunks per stage

    extern __shared__ char smem[];
    GSeg sg; int lz;
    {
        int z = blockIdx.z;
        if (z < zs1)      { sg = s0; lz = z; }
        else if (z < zs2) { sg = s1; lz = z - zs1; }
        else              { sg = s2; lz = z - zs2; }
    }
    int zb = lz / Hc, zh = lz - zb * Hc;
    Ah += zb*saB + zh*saH;
    if (NPASS == 2) Al += zb*saB + zh*saH;
    const __half* Bh = sg.Bh + zb*sg.sbB + zh*sg.sbH;
    float*  C  = sg.C;
    __half* Dh = sg.Dh;
    __half* Dl = sg.Dl;
    int ldb = sg.ldb, mode = sg.mode;
    size_t cOff = (size_t)zb * scB + (size_t)zh * scH;

    int m0 = blockIdx.y * BM, n0 = blockIdx.x * BN;
    if (mode == 1 && n0 >= m0 + BM) return;
    if (mode == 2 && (m0 + n0 + BM + BN - 2) < (N - 1)) return;
    int Kt = (mode == 3) ? (K < m0 + BM ? K : m0 + BM) : K;
    int nT = Kt / BK;

    uint32_t su = (uint32_t)__cvta_generic_to_shared(smem);
    int tid = threadIdx.x, warp = tid >> 5, lane = tid & 31;
    int wm = warp >> 2, wn = warp & 3;           // 2 x 4 warps; warp tile 64 x (8*NI)

    auto load_tile = [&](int t, int s) {
        int k0 = t * BK;
        uint32_t base = su + s * STB;
        #pragma unroll
        for (int it = 0; it < NCH / 256; it++) {
            int c = tid + it * 256;
            const __half* src; uint32_t off; int rc, rowBase, ld;
            if (c < 512)                       { src = Ah; off = 0;          rc = c;       rowBase = m0; ld = lda; }
            else if (NPASS == 2 && c < 1024)   { src = Al; off = MATB;       rc = c - 512; rowBase = m0; ld = lda; }
            else                               { src = Bh; off = NPASS*MATB; rc = c - ACH; rowBase = n0; ld = ldb; }
            int row = rc >> 2, ch = rc & 3;      // 4 x 16B chunks per 64B row
            uint32_t dst = base + off + row * (BKP*2) + ch * 16;
            const void* p = src + (size_t)(rowBase + row) * ld + (k0 + ch * 8);
            asm volatile("cp.async.cg.shared.global [%0], [%1], 16;" :: "r"(dst), "l"(p));
        }
    };

    float acc[4][NI][4];
    #pragma unroll
    for (int i = 0; i < 4; i++)
        #pragma unroll
        for (int j = 0; j < NI; j++)
            #pragma unroll
            for (int u = 0; u < 4; u++) acc[i][j][u] = 0.f;

    #pragma unroll
    for (int s = 0; s < STAGES - 1; s++) {
        if (s < nT) load_tile(s, s);
        asm volatile("cp.async.commit_group;" ::: "memory");
    }

    int aoffBase = ((wm*64 + (lane & 15)) * BKP + ((lane >> 4) << 3)) * 2;
    int bq = lane >> 3, brr = lane & 7;
    int boffBase = ((wn*8*NI + brr + ((bq >> 1) << 3)) * BKP + ((bq & 1) << 3)) * 2;

    for (int t = 0; t < nT; t++) {
        asm volatile("cp.async.wait_group %0;" :: "n"(STAGES - 2));
        __syncthreads();
        int nxt = t + STAGES - 1;
        if (nxt < nT) load_tile(nxt, nxt % STAGES);
        asm volatile("cp.async.commit_group;" ::: "memory");

        uint32_t sb = su + (t % STAGES) * STB;
        #pragma unroll
        for (int ks = 0; ks < BK; ks += 16) {
            uint32_t bf[NI][2];
            #pragma unroll
            for (int np = 0; np < NI/2; np++) {
                uint32_t bt[4];
                ldsm4(bt, sb + NPASS*MATB + boffBase + (np*16*BKP + ks) * 2);
                bf[2*np][0]   = bt[0]; bf[2*np][1]   = bt[1];
                bf[2*np+1][0] = bt[2]; bf[2*np+1][1] = bt[3];
            }
            #pragma unroll
            for (int pass = 0; pass < NPASS; pass++) {
                uint32_t af[4][4];
                #pragma unroll
                for (int mi = 0; mi < 4; mi++)
                    ldsm4(af[mi], sb + pass*MATB + aoffBase + (mi*16*BKP + ks) * 2);
                #pragma unroll
                for (int mi = 0; mi < 4; mi++)
                    #pragma unroll
                    for (int ni = 0; ni < NI; ni++)
                        mma16816(acc[mi][ni], af[mi], bf[ni][0], bf[ni][1]);
            }
        }
    }

    // epilogue (optional deferred-softmax row scaling)
    long rsOff = (long)lz * NSEQ;
    int g = lane >> 2, tq = lane & 3;
    #pragma unroll
    for (int mi = 0; mi < 4; mi++) {
        int r0 = m0 + wm*64 + mi*16 + g;
        float inv0 = 1.f, inv8 = 1.f;
        if (Rsum) {
            inv0 = __frcp_rn(Rsum[rsOff + r0]);
            inv8 = __frcp_rn(Rsum[rsOff + r0 + 8]);
        }
        #pragma unroll
        for (int ni = 0; ni < NI; ni++) {
            int c0 = n0 + wn*8*NI + ni*8 + 2*tq;
            #pragma unroll
            for (int hrow = 0; hrow < 2; hrow++) {
                size_t o = cOff + (size_t)(r0 + 8*hrow) * ldc + c0;
                float sc = hrow ? inv8 : inv0;
                float v0 = acc[mi][ni][2*hrow] * sc, v1 = acc[mi][ni][2*hrow + 1] * sc;
                if (C) *(float2*)(C + o) = make_float2(v0, v1);
                if (Dh) {
                    __half2 hh;
                    hh.x = __float2half_rn(v0);  hh.y = __float2half_rn(v1);
                    *(__half2*)(Dh + o) = hh;
                    if (Dl) {
                        __half2 ll;
                        ll.x = __float2half_rn(v0 - __half2float(hh.x));
                        ll.y = __float2half_rn(v1 - __half2float(hh.y));
                        *(__half2*)(Dl + o) = ll;
                    }
                }
            }
        }
    }
}

// ---------------- merged input split: fp32 -> fp16 hi (+ optional lo) ----------------
struct SJob { const float* s; __half* h; __half* l; int n4; };

__global__ void split_multi(SJob j0, SJob j1, SJob j2, SJob j3, SJob j4, SJob j5)
{
    SJob j;
    switch (blockIdx.y) {
        case 0: j = j0; break; case 1: j = j1; break; case 2: j = j2; break;
        case 3: j = j3; break; case 4: j = j4; break; default: j = j5; break;
    }
    int i = blockIdx.x * 256 + threadIdx.x;
    if (i >= j.n4) return;
    float4 v = ((const float4*)j.s)[i];
    __half2 h01, h23;
    h01.x = __float2half_rn(v.x);  h01.y = __float2half_rn(v.y);
    h23.x = __float2half_rn(v.z);  h23.y = __float2half_rn(v.w);
    ((__half2*)j.h)[2*i]   = h01;
    ((__half2*)j.h)[2*i+1] = h23;
    if (j.l) {
        __half2 l01, l23;
        l01.x = __float2half_rn(v.x - __half2float(h01.x));
        l01.y = __float2half_rn(v.y - __half2float(h01.y));
        l23.x = __float2half_rn(v.z - __half2float(h23.x));
        l23.y = __float2half_rn(v.w - __half2float(h23.y));
        ((__half2*)j.l)[2*i]   = l01;
        ((__half2*)j.l)[2*i+1] = l23;
    }
}

// ---------------- V transpose: tmpV (b, j, h*64+d) -> Vth [b][h][d][j] fp16 ----------------
__global__ void transpose_v(const float* __restrict__ V)
{
    __shared__ float tile[32][33];
    int bh = blockIdx.z;
    int b = bh >> 4, h = bh & 15;
    int j0 = blockIdx.x * 32, d0 = blockIdx.y * 32;
    for (int r = threadIdx.y; r < 32; r += 8)
        tile[r][threadIdx.x] =
            V[((size_t)(b * NSEQ) + j0 + r) * DIM + h * DH + d0 + threadIdx.x];
    __syncthreads();
    for (int r = threadIdx.y; r < 32; r += 8) {
        size_t o = ((size_t)(bh * DH) + d0 + r) * NSEQ + j0 + threadIdx.x;
        g_Vth[o] = __float2half_rn(tile[threadIdx.x][r]);
    }
}

// ================= QE: smem-blocked, coalesced =================
#define QE_SMEM (39296 + 64*64*4)     // tabs[151][65] (pad) + q[64][64]

__global__ __launch_bounds__(256)
void qe_kernel2(const float* __restrict__ Q,
                const float* __restrict__ Tb, const float* __restrict__ Tp,
                const float* __restrict__ To, const float* __restrict__ Ts)
{
    extern __shared__ float sm[];
    float* tabs = sm;                 // [151][65]
    float* qs   = sm + 9824;          // [64][64]
    int i0 = blockIdx.x * 64, h = blockIdx.y, b = blockIdx.z;
    int tid = threadIdx.x;

    for (int idx = tid; idx < QE_S * 64; idx += 256) {
        int s = idx >> 6, d = idx & 63;
        const float* tab; int r, rows;
        if (s < 17)       { tab = Tb; r = s;       rows = 16; }
        else if (s < 113) { tab = Tp; r = s - 17;  rows = 95; }
        else if (s < 138) { tab = To; r = s - 113; rows = 24; }
        else              { tab = Ts; r = s - 138; rows = 12; }
        tabs[s * 65 + d] = (r < rows) ? tab[r * 64 + d] : 0.f;
    }
    for (int idx = tid; idx < 64 * 64; idx += 256) {
        int ii = idx >> 6, d = idx & 63;
        qs[idx] = Q[((size_t)(b * NSEQ) + i0 + ii) * DIM + h * DH + d];
    }
    __syncthreads();

    int ty = tid >> 5, tx = tid & 31;
    float acc[5][8];
    #pragma unroll
    for (int si = 0; si < 5; si++)
        #pragma unroll
        for (int ii = 0; ii < 8; ii++) acc[si][ii] = 0.f;
    int sc[5];
    #pragma unroll
    for (int si = 0; si < 5; si++) { int s = tx + si * 32; sc[si] = (s < QE_S) ? s : 0; }

    const float* qrow = qs + ty * 8 * 64;
    #pragma unroll 4
    for (int d = 0; d < 64; d++) {
        float q8[8];
        #pragma unroll
        for (int ii = 0; ii < 8; ii++) q8[ii] = qrow[ii * 64 + d];
        #pragma unroll
        for (int si = 0; si < 5; si++) {
            float tv = tabs[sc[si] * 65 + d];
            #pragma unroll
            for (int ii = 0; ii < 8; ii++) acc[si][ii] += tv * q8[ii];
        }
    }

    size_t base = ((size_t)(b * NH + h) * NSEQ + i0 + ty * 8) * QE_PAD;
    #pragma unroll
    for (int si = 0; si < 5; si++) {
        int s = tx + si * 32;
        if (s < QE_S) {
            #pragma unroll
            for (int ii = 0; ii < 8; ii++)
                g_QE[base + (size_t)ii * QE_PAD + s] = acc[si][ii];
        }
    }
}

// ---------------- fused bias + skew + softmax (unnormalized) ----------------
// fp32 score/QEr reads (reverted); exp via ex2.approx.f16x2 (2 exps / MUFU op),
// writing fp16 P pairs directly. Row sums to g_rsum; normalization in P@V epilogue.
__global__ __launch_bounds__(256)
void bias_softmax(const int* __restrict__ rb, const int* __restrict__ rp,
                  const int* __restrict__ ro, const int* __restrict__ rs)
{
    int i = blockIdx.x, b = blockIdx.y;
    __shared__ short sIdx[4][NSEQ];
    __shared__ float row[NSEQ];
    __shared__ float qe[QE_PAD];
    __shared__ float red[8];
    int tid = threadIdx.x;
    int Li = i + 1;
    int jEnd = (Li + 127) & ~127;
    size_t iBase = ((size_t)(b * NSEQ) + i) * NSEQ;

    for (int j = tid; j < Li; j += 256) {
        sIdx[0][j] = (short)rb[iBase + j];
        sIdx[1][j] = (short)(17  + rp[iBase + j]);
        sIdx[2][j] = (short)(113 + ro[iBase + j]);
        sIdx[3][j] = (short)(138 + rs[iBase + j]);
    }
    // tail fill: exp of (-1e9 - m)*log2e underflows to exactly 0 in fp16
    for (int j = Li + tid; j < jEnd; j += 256) row[j] = -1.0e9f;

    for (int h = 0; h < NH; h++) {
        size_t base  = (size_t)((b * NH + h) * NSEQ) + i;
        size_t sBase = base * NSEQ;
        __syncthreads();
        if (tid < QE_S) qe[tid] = g_QE[base * QE_PAD + tid];
        __syncthreads();

        const float* qer = &g_QEr[sBase + (NSEQ - 1 - i)];
        float lmax = -3.0e38f;
        for (int j = tid; j < Li; j += 256) {
            float v = g_S[sBase + j] + qer[j]
                    + qe[sIdx[0][j]] + qe[sIdx[1][j]] + qe[sIdx[2][j]] + qe[sIdx[3][j]];
            v *= 0.125f;
            row[j] = v;
            lmax = fmaxf(lmax, v);
        }
        #pragma unroll
        for (int o = 16; o > 0; o >>= 1)
            lmax = fmaxf(lmax, __shfl_xor_sync(0xffffffffu, lmax, o));
        if ((tid & 31) == 0) red[tid >> 5] = lmax;
        __syncthreads();
        float m = red[0];
        #pragma unroll
        for (int w = 1; w < 8; w++) m = fmaxf(m, red[w]);
        __syncthreads();                         // red[] safe to reuse

        // exp pairs via f16x2 MUFU; store fp16 P directly; fp32 sum
        float lsum = 0.f;
        int pEnd = jEnd >> 1;
        for (int p = tid; p < pEnd; p += 256) {
            int j = p * 2;
            float2 vv = *(float2*)&row[j];
            __half2 xh = __floats2half2_rn((vv.x - m) * 1.44269504f,
                                           (vv.y - m) * 1.44269504f);
            uint32_t xu = *(uint32_t*)&xh, eu;
            asm("ex2.approx.f16x2 %0, %1;" : "=r"(eu) : "r"(xu));
            *(uint32_t*)&g_Ph[sBase + j] = eu;
            float2 ef = __half22float2(*(__half2*)&eu);
            lsum += ef.x + ef.y;
        }
        #pragma unroll
        for (int o = 16; o > 0; o >>= 1) lsum += __shfl_xor_sync(0xffffffffu, lsum, o);
        if ((tid & 31) == 0) red[tid >> 5] = lsum;
        __syncthreads();
        if (tid == 0) {
            float tot = 0.f;
            #pragma unroll
            for (int w = 0; w < 8; w++) tot += red[w];
            g_rsum[(size_t)(b * NH + h) * NSEQ + i] = tot;
        }
    }
}

// ---------------- host orchestration ----------------
extern "C" void kernel_launch(void* const* d_in, const int* in_sizes, int n_in,
                              void* d_out, int out_size)
{
    (void)in_sizes; (void)n_in; (void)out_size;
    const float* x   = (const float*)d_in[0];
    const int*   rb  = (const int*)d_in[1];
    const int*   rp  = (const int*)d_in[2];
    const int*   ro  = (const int*)d_in[3];
    const int*   rs  = (const int*)d_in[4];
    const float* Wq  = (const float*)d_in[5];
    const float* Wk  = (const float*)d_in[6];
    const float* Wv  = (const float*)d_in[7];
    const float* Wo  = (const float*)d_in[8];
    const float* Er  = (const float*)d_in[9];
    const float* Erb = (const float*)d_in[10];
    const float* Erp = (const float*)d_in[11];
    const float* Ero = (const float*)d_in[12];
    const float* Ers = (const float*)d_in[13];
    float* out = (float*)d_out;

    const int SMEM_42 = STAGES * (2*MATB + 128*BKP*2);   // 92160
    const int SMEM_41 = STAGES * (1*MATB + 128*BKP*2);   // 61440
    const int SMEM_21 = STAGES * (1*MATB +  64*BKP*2);   // 46080
    cudaFuncSetAttribute((const void*)gemm_fp16<4,2>, cudaFuncAttributeMaxDynamicSharedMemorySize, SMEM_42);
    cudaFuncSetAttribute((const void*)gemm_fp16<4,1>, cudaFuncAttributeMaxDynamicSharedMemorySize, SMEM_41);
    cudaFuncSetAttribute((const void*)gemm_fp16<2,1>, cudaFuncAttributeMaxDynamicSharedMemorySize, SMEM_21);
    cudaFuncSetAttribute((const void*)qe_kernel2,     cudaFuncAttributeMaxDynamicSharedMemorySize, QE_SMEM);

    float *pTmpQ, *pTmpV, *pS, *pQEr, *pRsum;
    __half *pxh, *pxl, *pWh, *pErh, *pQh, *pQl, *pKh, *pVth, *pAOh, *pPh;
    cudaGetSymbolAddress((void**)&pTmpQ, g_tmpQ);
    cudaGetSymbolAddress((void**)&pTmpV, g_tmpV);
    cudaGetSymbolAddress((void**)&pS,    g_S);
    cudaGetSymbolAddress((void**)&pQEr,  g_QEr);
    cudaGetSymbolAddress((void**)&pRsum, g_rsum);
    cudaGetSymbolAddress((void**)&pxh,   g_xh);
    cudaGetSymbolAddress((void**)&pxl,   g_xl);
    cudaGetSymbolAddress((void**)&pWh,   g_Wh);
    cudaGetSymbolAddress((void**)&pErh,  g_Erh);
    cudaGetSymbolAddress((void**)&pQh,   g_Qh);
    cudaGetSymbolAddress((void**)&pQl,   g_Ql);
    cudaGetSymbolAddress((void**)&pKh,   g_Kh);
    cudaGetSymbolAddress((void**)&pVth,  g_Vth);
    cudaGetSymbolAddress((void**)&pAOh,  g_AOh);
    cudaGetSymbolAddress((void**)&pPh,   g_Ph);

    const int MB  = BATCH * NSEQ;   // 2048
    const int WSZ = DIM * DIM;

    long saB = (long)NSEQ * DIM, saH = DH;
    long scB = (long)NH * NSEQ * NSEQ, scH = (long)NSEQ * NSEQ;
    dim3 blk(256);

    // 0) split inputs (x needs hi+lo; W/Er hi only)
    {
        SJob j0 = { x,  pxh,         pxl,     MB * DIM / 4 };
        SJob j1 = { Wq, pWh + 0*WSZ, nullptr, WSZ / 4 };
        SJob j2 = { Wk, pWh + 1*WSZ, nullptr, WSZ / 4 };
        SJob j3 = { Wv, pWh + 2*WSZ, nullptr, WSZ / 4 };
        SJob j4 = { Wo, pWh + 3*WSZ, nullptr, WSZ / 4 };
        SJob j5 = { Er, pErh,        nullptr, NSEQ * DH / 4 };
        split_multi<<<dim3(2048, 6), 256>>>(j0, j1, j2, j3, j4, j5);
    }

    // 1) fused Q/K/V projections: z=0 Q, z=1 K, z=2 V
    {
        GSeg sq = { pWh + 0*WSZ, pTmpQ, pQh, pQl, DIM, 0, 0, 0 };
        GSeg sk = { pWh + 1*WSZ, nullptr, pKh, nullptr, DIM, 0, 0, 0 };
        GSeg sv = { pWh + 2*WSZ, pTmpV, nullptr, nullptr, DIM, 0, 0, 0 };
        gemm_fp16<4,2><<<dim3(DIM/128, MB/BM, 3), blk, SMEM_42>>>(
            pxh, pxl, sq, sk, sv, 1, 2,
            DIM, DIM, DIM, DIM, 0, 0, 0, 0, 1, nullptr);
    }
    // 2) QE tables
    qe_kernel2<<<dim3(NSEQ / 64, NH, BATCH), 256, QE_SMEM>>>(pTmpQ, Erb, Erp, Ero, Ers);
    // 3) transpose V -> fp16
    transpose_v<<<dim3(NSEQ / 32, DH / 32, BATCH * NH), dim3(32, 8)>>>(pTmpV);
    // 4) fused scores (z<32, causal skip) + QEr (z>=32, anti-diag skip), fp32 out
    {
        GSeg ss  = { pKh,  pS,   nullptr, nullptr, DIM, saB, saH, 1 };
        GSeg sqe = { pErh, pQEr, nullptr, nullptr, DH,  0,   0,   2 };
        gemm_fp16<4,2><<<dim3(NSEQ/128, NSEQ/BM, 64), blk, SMEM_42>>>(
            pQh, pQl, ss, sqe, ss, 32, 64,
            NSEQ, DH, DIM, NSEQ, saB, saH, scB, scH, NH, nullptr);
    }
    // 5) bias + softmax -> unnormalized P (fp16, f16x2 exp) + row sums
    bias_softmax<<<dim3(NSEQ, BATCH), 256>>>(rb, rp, ro, rs);
    // 6) attn_out = (P @ V) / rsum  (single-pass A, BN=64, causal K-limit, fp16 out)
    {
        GSeg sv = { pVth, nullptr, pAOh, nullptr, NSEQ,
                    (long)NH * DH * NSEQ, (long)DH * NSEQ, 3 };
        gemm_fp16<2,1><<<dim3(1, NSEQ/BM, BATCH*NH), blk, SMEM_21>>>(
            pPh, nullptr, sv, sv, sv, 32, 64,
            DH, NSEQ, NSEQ, DIM,
            scB, scH, (long)NSEQ * DIM, (long)DH, NH, pRsum);
    }
    // 7) out = attn_out @ Wo^T  (single-pass A: AO fp16 only; BN=128)
    {
        GSeg so = { pWh + 3*WSZ, out, nullptr, nullptr, DIM, 0, 0, 0 };
        gemm_fp16<4,1><<<dim3(DIM/128, MB/BM, 1), blk, SMEM_41>>>(
            pAOh, nullptr, so, so, so, 1, 2,
            DIM, DIM, DIM, DIM, 0, 0, 0, 0, 1, nullptr);
    }
}

// round 17
// speedup vs baseline: 1.8143x; 1.2827x over previous
#include <cuda_runtime.h>
#include <cuda_fp16.h>
#include <stdint.h>
#include <stddef.h>

#define BATCH 2
#define NSEQ  1024
#define DIM   1024
#define NH    16
#define DH    64
#define QE_S  151
#define QE_PAD 152

#define BM 128
#define BK 32
#define BKP 40                       // padded row: 40 halfs = 80 B
#define STAGES 3
#define MATB (BM*BKP*2)              // 10240 B for the A matrix per stage

// ---------------- static scratch (no cudaMalloc allowed) ----------------
__device__ __align__(128) __half g_xh[BATCH*NSEQ*DIM];
__device__ __align__(128) __half g_Wh[4][DIM*DIM];                  // q,k,v,o
__device__ __align__(128) __half g_Erh[NSEQ*DH];
__device__ __align__(128) __half g_Qh[BATCH*NSEQ*DIM];
__device__ __align__(128) __half g_Kh[BATCH*NSEQ*DIM];
__device__ __align__(128) __half g_Vf[BATCH*NSEQ*DIM];              // V, (b,j,dim) fp16
__device__ __align__(128) __half g_Vth[BATCH*NH*DH*NSEQ];           // [b][h][d][j]
__device__ __align__(128) __half g_AOh[BATCH*NSEQ*DIM];
__device__ __align__(128) float  g_QE[BATCH*NH*NSEQ*QE_PAD];
__device__ __align__(128) float  g_S [BATCH*NH*NSEQ*NSEQ];          // scores fp32
__device__ __align__(128) float  g_QEr[BATCH*NH*NSEQ*NSEQ];         // QEr fp32
__device__ __align__(128) __half g_Ph[BATCH*NH*NSEQ*NSEQ];
__device__ __align__(128) float  g_rsum[BATCH*NH*NSEQ];

// ---------------- helpers ----------------
__device__ __forceinline__ void mma16816(float c[4], const uint32_t a[4],
                                         uint32_t b0, uint32_t b1)
{
    asm volatile(
        "mma.sync.aligned.m16n8k16.row.col.f32.f16.f16.f32 "
        "{%0,%1,%2,%3}, {%4,%5,%6,%7}, {%8,%9}, {%0,%1,%2,%3};\n"
        : "+f"(c[0]), "+f"(c[1]), "+f"(c[2]), "+f"(c[3])
        : "r"(a[0]), "r"(a[1]), "r"(a[2]), "r"(a[3]), "r"(b0), "r"(b1));
}

__device__ __forceinline__ void ldsm4(uint32_t* r, uint32_t addr)
{
    asm volatile("ldmatrix.sync.aligned.m8n8.x4.shared.b16 {%0,%1,%2,%3}, [%4];\n"
                 : "=r"(r[0]), "=r"(r[1]), "=r"(r[2]), "=r"(r[3]) : "r"(addr));
}

// per-z-segment GEMM descriptor
struct GSeg {
    const __half* Bh;     // B operand
    float*  C;            // optional fp32 out
    __half* Dh;           // optional fp16 out
    int  ldb;
    long sbB, sbH;        // B (batch, head) strides
    int  mode;            // 0 none, 1 causal skip, 2 anti-diag skip, 3 causal K-limit
};

// ========== pipelined fp16 GEMM: C[M,N] = A[M,K] @ B[N,K]^T (fp32 accum) ==========
// blockIdx.z selects segment (s0/s1/s2) via zs1/zs2; local z -> (zb,zh).
// Rsum != null: epilogue scales output row r by 1/Rsum[lz*NSEQ + r].
template<int NI>
__global__ __launch_bounds__(256, 2)
void gemm_fp16(const __half* __restrict__ Ah,
               GSeg s0, GSeg s1, GSeg s2, int zs1, int zs2,
               int N, int K, int lda, int ldc,
               long saB, long saH, long scB, long scH, int Hc,
               const float* __restrict__ Rsum)
{
    constexpr int BN   = 32 * NI;
    constexpr int BMAT = BN * BKP * 2;           // B bytes per stage
    constexpr int STB  = MATB + BMAT;            // stage bytes
    constexpr int NCH  = 512 + BN * 4;           // 16B chunks per stage

    extern __shared__ char smem[];
    GSeg sg; int lz;
    {
        int z = blockIdx.z;
        if (z < zs1)      { sg = s0; lz = z; }
        else if (z < zs2) { sg = s1; lz = z - zs1; }
        else              { sg = s2; lz = z - zs2; }
    }
    int zb = lz / Hc, zh = lz - zb * Hc;
    Ah += zb*saB + zh*saH;
    const __half* Bh = sg.Bh + zb*sg.sbB + zh*sg.sbH;
    float*  C  = sg.C;
    __half* Dh = sg.Dh;
    int ldb = sg.ldb, mode = sg.mode;
    size_t cOff = (size_t)zb * scB + (size_t)zh * scH;

    int m0 = blockIdx.y * BM, n0 = blockIdx.x * BN;
    if (mode == 1 && n0 >= m0 + BM) return;
    if (mode == 2 && (m0 + n0 + BM + BN - 2) < (N - 1)) return;
    int Kt = (mode == 3) ? (K < m0 + BM ? K : m0 + BM) : K;
    int nT = Kt / BK;

    uint32_t su = (uint32_t)__cvta_generic_to_shared(smem);
    int tid = threadIdx.x, warp = tid >> 5, lane = tid & 31;
    int wm = warp >> 2, wn = warp & 3;           // 2 x 4 warps; warp tile 64 x (8*NI)

    auto load_tile = [&](int t, int s) {
        int k0 = t * BK;
        uint32_t base = su + s * STB;
        #pragma unroll
        for (int it = 0; it < NCH / 256; it++) {
            int c = tid + it * 256;
            const __half* src; uint32_t off; int rc, rowBase, ld;
            if (c < 512) { src = Ah; off = 0;    rc = c;       rowBase = m0; ld = lda; }
            else         { src = Bh; off = MATB; rc = c - 512; rowBase = n0; ld = ldb; }
            int row = rc >> 2, ch = rc & 3;      // 4 x 16B chunks per 64B row
            uint32_t dst = base + off + row * (BKP*2) + ch * 16;
            const void* p = src + (size_t)(rowBase + row) * ld + (k0 + ch * 8);
            asm volatile("cp.async.cg.shared.global [%0], [%1], 16;" :: "r"(dst), "l"(p));
        }
    };

    float acc[4][NI][4];
    #pragma unroll
    for (int i = 0; i < 4; i++)
        #pragma unroll
        for (int j = 0; j < NI; j++)
            #pragma unroll
            for (int u = 0; u < 4; u++) acc[i][j][u] = 0.f;

    #pragma unroll
    for (int s = 0; s < STAGES - 1; s++) {
        if (s < nT) load_tile(s, s);
        asm volatile("cp.async.commit_group;" ::: "memory");
    }

    int aoffBase = ((wm*64 + (lane & 15)) * BKP + ((lane >> 4) << 3)) * 2;
    int bq = lane >> 3, brr = lane & 7;
    int boffBase = ((wn*8*NI + brr + ((bq >> 1) << 3)) * BKP + ((bq & 1) << 3)) * 2;

    for (int t = 0; t < nT; t++) {
        asm volatile("cp.async.wait_group %0;" :: "n"(STAGES - 2));
        __syncthreads();
        int nxt = t + STAGES - 1;
        if (nxt < nT) load_tile(nxt, nxt % STAGES);
        asm volatile("cp.async.commit_group;" ::: "memory");

        uint32_t sb = su + (t % STAGES) * STB;
        #pragma unroll
        for (int ks = 0; ks < BK; ks += 16) {
            uint32_t bf[NI][2];
            #pragma unroll
            for (int np = 0; np < NI/2; np++) {
                uint32_t bt[4];
                ldsm4(bt, sb + MATB + boffBase + (np*16*BKP + ks) * 2);
                bf[2*np][0]   = bt[0]; bf[2*np][1]   = bt[1];
                bf[2*np+1][0] = bt[2]; bf[2*np+1][1] = bt[3];
            }
            uint32_t af[4][4];
            #pragma unroll
            for (int mi = 0; mi < 4; mi++)
                ldsm4(af[mi], sb + aoffBase + (mi*16*BKP + ks) * 2);
            #pragma unroll
            for (int mi = 0; mi < 4; mi++)
                #pragma unroll
                for (int ni = 0; ni < NI; ni++)
                    mma16816(acc[mi][ni], af[mi], bf[ni][0], bf[ni][1]);
        }
    }

    // epilogue (optional deferred-softmax row scaling)
    long rsOff = (long)lz * NSEQ;
    int g = lane >> 2, tq = lane & 3;
    #pragma unroll
    for (int mi = 0; mi < 4; mi++) {
        int r0 = m0 + wm*64 + mi*16 + g;
        float inv0 = 1.f, inv8 = 1.f;
        if (Rsum) {
            inv0 = __frcp_rn(Rsum[rsOff + r0]);
            inv8 = __frcp_rn(Rsum[rsOff + r0 + 8]);
        }
        #pragma unroll
        for (int ni = 0; ni < NI; ni++) {
            int c0 = n0 + wn*8*NI + ni*8 + 2*tq;
            #pragma unroll
            for (int hrow = 0; hrow < 2; hrow++) {
                size_t o = cOff + (size_t)(r0 + 8*hrow) * ldc + c0;
                float sc = hrow ? inv8 : inv0;
                float v0 = acc[mi][ni][2*hrow] * sc, v1 = acc[mi][ni][2*hrow + 1] * sc;
                if (C) *(float2*)(C + o) = make_float2(v0, v1);
                if (Dh) {
                    __half2 hh;
                    hh.x = __float2half_rn(v0);  hh.y = __float2half_rn(v1);
                    *(__half2*)(Dh + o) = hh;
                }
            }
        }
    }
}

// ---------------- merged input split: fp32 -> fp16 ----------------
struct SJob { const float* s; __half* h; int n4; };

__global__ void split_multi(SJob j0, SJob j1, SJob j2, SJob j3, SJob j4, SJob j5)
{
    SJob j;
    switch (blockIdx.y) {
        case 0: j = j0; break; case 1: j = j1; break; case 2: j = j2; break;
        case 3: j = j3; break; case 4: j = j4; break; default: j = j5; break;
    }
    int i = blockIdx.x * 256 + threadIdx.x;
    if (i >= j.n4) return;
    float4 v = ((const float4*)j.s)[i];
    __half2 h01, h23;
    h01.x = __float2half_rn(v.x);  h01.y = __float2half_rn(v.y);
    h23.x = __float2half_rn(v.z);  h23.y = __float2half_rn(v.w);
    ((__half2*)j.h)[2*i]   = h01;
    ((__half2*)j.h)[2*i+1] = h23;
}

// ---------------- V transpose: Vf (b, j, h*64+d) fp16 -> Vth [b][h][d][j] fp16 ----------------
__global__ void transpose_v(const __half* __restrict__ V)
{
    __shared__ __half tile[32][34];
    int bh = blockIdx.z;
    int b = bh >> 4, h = bh & 15;
    int j0 = blockIdx.x * 32, d0 = blockIdx.y * 32;
    for (int r = threadIdx.y; r < 32; r += 8)
        tile[r][threadIdx.x] =
            V[((size_t)(b * NSEQ) + j0 + r) * DIM + h * DH + d0 + threadIdx.x];
    __syncthreads();
    for (int r = threadIdx.y; r < 32; r += 8) {
        size_t o = ((size_t)(bh * DH) + d0 + r) * NSEQ + j0 + threadIdx.x;
        g_Vth[o] = tile[threadIdx.x][r];
    }
}

// ================= QE: smem-blocked, coalesced; reads fp16 Q =================
#define QE_SMEM (39296 + 64*64*4)     // tabs[151][65] (pad) + q[64][64] fp32

__global__ __launch_bounds__(256)
void qe_kernel2(const __half* __restrict__ Q,
                const float* __restrict__ Tb, const float* __restrict__ Tp,
                const float* __restrict__ To, const float* __restrict__ Ts)
{
    extern __shared__ float sm[];
    float* tabs = sm;                 // [151][65]
    float* qs   = sm + 9824;          // [64][64]
    int i0 = blockIdx.x * 64, h = blockIdx.y, b = blockIdx.z;
    int tid = threadIdx.x;

    for (int idx = tid; idx < QE_S * 64; idx += 256) {
        int s = idx >> 6, d = idx & 63;
        const float* tab; int r, rows;
        if (s < 17)       { tab = Tb; r = s;       rows = 16; }
        else if (s < 113) { tab = Tp; r = s - 17;  rows = 95; }
        else if (s < 138) { tab = To; r = s - 113; rows = 24; }
        else              { tab = Ts; r = s - 138; rows = 12; }
        tabs[s * 65 + d] = (r < rows) ? tab[r * 64 + d] : 0.f;
    }
    for (int idx = tid; idx < 64 * 64; idx += 256) {
        int ii = idx >> 6, d = idx & 63;
        qs[idx] = __half2float(Q[((size_t)(b * NSEQ) + i0 + ii) * DIM + h * DH + d]);
    }
    __syncthreads();

    int ty = tid >> 5, tx = tid & 31;
    float acc[5][8];
    #pragma unroll
    for (int si = 0; si < 5; si++)
        #pragma unroll
        for (int ii = 0; ii < 8; ii++) acc[si][ii] = 0.f;
    int sc[5];
    #pragma unroll
    for (int si = 0; si < 5; si++) { int s = tx + si * 32; sc[si] = (s < QE_S) ? s : 0; }

    const float* qrow = qs + ty * 8 * 64;
    #pragma unroll 4
    for (int d = 0; d < 64; d++) {
        float q8[8];
        #pragma unroll
        for (int ii = 0; ii < 8; ii++) q8[ii] = qrow[ii * 64 + d];
        #pragma unroll
        for (int si = 0; si < 5; si++) {
            float tv = tabs[sc[si] * 65 + d];
            #pragma unroll
            for (int ii = 0; ii < 8; ii++) acc[si][ii] += tv * q8[ii];
        }
    }

    size_t base = ((size_t)(b * NH + h) * NSEQ + i0 + ty * 8) * QE_PAD;
    #pragma unroll
    for (int si = 0; si < 5; si++) {
        int s = tx + si * 32;
        if (s < QE_S) {
            #pragma unroll
            for (int ii = 0; ii < 8; ii++)
                g_QE[base + (size_t)ii * QE_PAD + s] = acc[si][ii];
        }
    }
}

// ---------------- fused bias + skew + softmax (unnormalized) ----------------
// Byte-packed index word per j (4 table slots, all < 256); float2-vectorized main
// loop; exp via ex2.approx.f16x2; fp16 P out + fp32 row sums (normalize in P@V).
__global__ __launch_bounds__(256)
void bias_softmax(const int* __restrict__ rb, const int* __restrict__ rp,
                  const int* __restrict__ ro, const int* __restrict__ rs)
{
    int i = blockIdx.x, b = blockIdx.y;
    __shared__ uint32_t sPack[NSEQ];
    __shared__ float row[NSEQ];
    __shared__ float qe[QE_PAD];
    __shared__ float red[8];
    int tid = threadIdx.x;
    int Li = i + 1;
    int jEnd = (Li + 127) & ~127;
    size_t iBase = ((size_t)(b * NSEQ) + i) * NSEQ;

    for (int j = tid; j < Li; j += 256) {
        uint32_t w = (uint32_t)rb[iBase + j]
                   | ((uint32_t)(17  + rp[iBase + j]) << 8)
                   | ((uint32_t)(113 + ro[iBase + j]) << 16)
                   | ((uint32_t)(138 + rs[iBase + j]) << 24);
        sPack[j] = w;
    }
    // tail fill (j >= Li): exp underflows to 0 in fp16
    for (int j = Li + tid; j < jEnd; j += 256) row[j] = -1.0e9f;

    for (int h = 0; h < NH; h++) {
        size_t base  = (size_t)((b * NH + h) * NSEQ) + i;
        size_t sBase = base * NSEQ;
        __syncthreads();
        if (tid < QE_S) qe[tid] = g_QE[base * QE_PAD + tid];
        __syncthreads();

        const float* qer = &g_QEr[sBase + (NSEQ - 1 - i)];
        float lmax = -3.0e38f;
        int pFull = Li >> 1;
        for (int p = tid; p < pFull; p += 256) {
            int j = p << 1;
            float2 sv = *(const float2*)&g_S[sBase + j];
            float q0 = qer[j], q1 = qer[j + 1];
            uint32_t w0 = sPack[j], w1 = sPack[j + 1];
            float v0 = sv.x + q0 + qe[w0 & 255] + qe[(w0 >> 8) & 255]
                     + qe[(w0 >> 16) & 255] + qe[w0 >> 24];
            float v1 = sv.y + q1 + qe[w1 & 255] + qe[(w1 >> 8) & 255]
                     + qe[(w1 >> 16) & 255] + qe[w1 >> 24];
            v0 *= 0.125f;  v1 *= 0.125f;
            *(float2*)&row[j] = make_float2(v0, v1);
            lmax = fmaxf(lmax, fmaxf(v0, v1));
        }
        if ((Li & 1) && tid == 0) {          // odd tail element
            int j = Li - 1;
            uint32_t w = sPack[j];
            float v = g_S[sBase + j] + qer[j] + qe[w & 255] + qe[(w >> 8) & 255]
                    + qe[(w >> 16) & 255] + qe[w >> 24];
            v *= 0.125f;
            row[j] = v;
            lmax = fmaxf(lmax, v);
        }
        #pragma unroll
        for (int o = 16; o > 0; o >>= 1)
            lmax = fmaxf(lmax, __shfl_xor_sync(0xffffffffu, lmax, o));
        if ((tid & 31) == 0) red[tid >> 5] = lmax;
        __syncthreads();
        float m = red[0];
        #pragma unroll
        for (int w = 1; w < 8; w++) m = fmaxf(m, red[w]);
        __syncthreads();                     // red[] safe to reuse

        // exp pairs via f16x2 MUFU; store fp16 P; fp32 sum
        float lsum = 0.f;
        int pEnd = jEnd >> 1;
        for (int p = tid; p < pEnd; p += 256) {
            int j = p * 2;
            float2 vv = *(float2*)&row[j];
            __half2 xh = __floats2half2_rn((vv.x - m) * 1.44269504f,
                                           (vv.y - m) * 1.44269504f);
            uint32_t xu = *(uint32_t*)&xh, eu;
            asm("ex2.approx.f16x2 %0, %1;" : "=r"(eu) : "r"(xu));
            *(uint32_t*)&g_Ph[sBase + j] = eu;
            float2 ef = __half22float2(*(__half2*)&eu);
            lsum += ef.x + ef.y;
        }
        #pragma unroll
        for (int o = 16; o > 0; o >>= 1) lsum += __shfl_xor_sync(0xffffffffu, lsum, o);
        if ((tid & 31) == 0) red[tid >> 5] = lsum;
        __syncthreads();
        if (tid == 0) {
            float tot = 0.f;
            #pragma unroll
            for (int w = 0; w < 8; w++) tot += red[w];
            g_rsum[(size_t)(b * NH + h) * NSEQ + i] = tot;
        }
    }
}

// ---------------- host orchestration ----------------
extern "C" void kernel_launch(void* const* d_in, const int* in_sizes, int n_in,
                              void* d_out, int out_size)
{
    (void)in_sizes; (void)n_in; (void)out_size;
    const float* x   = (const float*)d_in[0];
    const int*   rb  = (const int*)d_in[1];
    const int*   rp  = (const int*)d_in[2];
    const int*   ro  = (const int*)d_in[3];
    const int*   rs  = (const int*)d_in[4];
    const float* Wq  = (const float*)d_in[5];
    const float* Wk  = (const float*)d_in[6];
    const float* Wv  = (const float*)d_in[7];
    const float* Wo  = (const float*)d_in[8];
    const float* Er  = (const float*)d_in[9];
    const float* Erb = (const float*)d_in[10];
    const float* Erp = (const float*)d_in[11];
    const float* Ero = (const float*)d_in[12];
    const float* Ers = (const float*)d_in[13];
    float* out = (float*)d_out;

    const int SMEM_4 = STAGES * (MATB + 128*BKP*2);   // 61440
    const int SMEM_2 = STAGES * (MATB +  64*BKP*2);   // 46080
    cudaFuncSetAttribute((const void*)gemm_fp16<4>, cudaFuncAttributeMaxDynamicSharedMemorySize, SMEM_4);
    cudaFuncSetAttribute((const void*)gemm_fp16<2>, cudaFuncAttributeMaxDynamicSharedMemorySize, SMEM_2);
    cudaFuncSetAttribute((const void*)qe_kernel2,   cudaFuncAttributeMaxDynamicSharedMemorySize, QE_SMEM);

    float *pS, *pQEr, *pRsum;
    __half *pxh, *pWh, *pErh, *pQh, *pKh, *pVf, *pVth, *pAOh, *pPh;
    cudaGetSymbolAddress((void**)&pS,    g_S);
    cudaGetSymbolAddress((void**)&pQEr,  g_QEr);
    cudaGetSymbolAddress((void**)&pRsum, g_rsum);
    cudaGetSymbolAddress((void**)&pxh,   g_xh);
    cudaGetSymbolAddress((void**)&pWh,   g_Wh);
    cudaGetSymbolAddress((void**)&pErh,  g_Erh);
    cudaGetSymbolAddress((void**)&pQh,   g_Qh);
    cudaGetSymbolAddress((void**)&pKh,   g_Kh);
    cudaGetSymbolAddress((void**)&pVf,   g_Vf);
    cudaGetSymbolAddress((void**)&pVth,  g_Vth);
    cudaGetSymbolAddress((void**)&pAOh,  g_AOh);
    cudaGetSymbolAddress((void**)&pPh,   g_Ph);

    const int MB  = BATCH * NSEQ;   // 2048
    const int WSZ = DIM * DIM;

    long saB = (long)NSEQ * DIM, saH = DH;
    long scB = (long)NH * NSEQ * NSEQ, scH = (long)NSEQ * NSEQ;
    dim3 blk(256);

    // 0) convert inputs to fp16
    {
        SJob j0 = { x,  pxh,         MB * DIM / 4 };
        SJob j1 = { Wq, pWh + 0*WSZ, WSZ / 4 };
        SJob j2 = { Wk, pWh + 1*WSZ, WSZ / 4 };
        SJob j3 = { Wv, pWh + 2*WSZ, WSZ / 4 };
        SJob j4 = { Wo, pWh + 3*WSZ, WSZ / 4 };
        SJob j5 = { Er, pErh,        NSEQ * DH / 4 };
        split_multi<<<dim3(2048, 6), 256>>>(j0, j1, j2, j3, j4, j5);
    }

    // 1) fused Q/K/V projections (single pass): z=0 Q, z=1 K, z=2 V
    {
        GSeg sq = { pWh + 0*WSZ, nullptr, pQh, DIM, 0, 0, 0 };
        GSeg sk = { pWh + 1*WSZ, nullptr, pKh, DIM, 0, 0, 0 };
        GSeg sv = { pWh + 2*WSZ, nullptr, pVf, DIM, 0, 0, 0 };
        gemm_fp16<4><<<dim3(DIM/128, MB/BM, 3), blk, SMEM_4>>>(
            pxh, sq, sk, sv, 1, 2,
            DIM, DIM, DIM, DIM, 0, 0, 0, 0, 1, nullptr);
    }
    // 2) QE tables (reads fp16 Q)
    qe_kernel2<<<dim3(NSEQ / 64, NH, BATCH), 256, QE_SMEM>>>(pQh, Erb, Erp, Ero, Ers);
    // 3) transpose V (fp16 -> fp16)
    transpose_v<<<dim3(NSEQ / 32, DH / 32, BATCH * NH), dim3(32, 8)>>>(pVf);
    // 4) fused scores (z<32, causal skip) + QEr (z>=32, anti-diag skip), fp32 out
    {
        GSeg ss  = { pKh,  pS,   nullptr, DIM, saB, saH, 1 };
        GSeg sqe = { pErh, pQEr, nullptr, DH,  0,   0,   2 };
        gemm_fp16<4><<<dim3(NSEQ/128, NSEQ/BM, 64), blk, SMEM_4>>>(
            pQh, ss, sqe, ss, 32, 64,
            NSEQ, DH, DIM, NSEQ, saB, saH, scB, scH, NH, nullptr);
    }
    // 5) bias + softmax -> unnormalized P (fp16) + row sums
    bias_softmax<<<dim3(NSEQ, BATCH), 256>>>(rb, rp, ro, rs);
    // 6) attn_out = (P @ V) / rsum  (BN=64, causal K-limit, fp16 out)
    {
        GSeg sv = { pVth, nullptr, pAOh, NSEQ,
                    (long)NH * DH * NSEQ, (long)DH * NSEQ, 3 };
        gemm_fp16<2><<<dim3(1, NSEQ/BM, BATCH*NH), blk, SMEM_2>>>(
            pPh, sv, sv, sv, 32, 64,
            DH, NSEQ, NSEQ, DIM,
            scB, scH, (long)NSEQ * DIM, (long)DH, NH, pRsum);
    }
    // 7) out = attn_out @ Wo^T
    {
        GSeg so = { pWh + 3*WSZ, out, nullptr, DIM, 0, 0, 0 };
        gemm_fp16<4><<<dim3(DIM/128, MB/BM, 1), blk, SMEM_4>>>(
            pAOh, so, so, so, 1, 2,
            DIM, DIM, DIM, DIM, 0, 0, 0, 0, 1, nullptr);
    }
}